// round 3
// baseline (speedup 1.0000x reference)
#include <cuda_runtime.h>
#include <math.h>

#define NN 20000        // nodes per type
#define D  256          // feature dim
#define EE 320000       // edges per relation
#define ND (NN * D)

// ---------------- scratch (device globals: no allocation allowed) ----------------
__device__ __align__(16) float g_h0[ND];      // layer1 out, type 0
__device__ __align__(16) float g_h1[ND];      // layer1 out, type 1
__device__ __align__(16) float g_o2[ND];      // layer2 out, type 0 (logits)
__device__ __align__(16) float g_y0[ND];      // per-relation transformed features
__device__ __align__(16) float g_y1[ND];
__device__ __align__(16) float g_y2[ND];
__device__ __align__(16) float g_y3[ND];
__device__ __align__(16) float g_Wc1[2 * D * D];  // combined root weights, layer1 (t=0, t=1)
__device__ __align__(16) float g_Wc2[D * D];      // combined root weights, layer2 (t=0)
__device__ float g_bc1[2 * D];
__device__ float g_bc2[D];

// ---------------- tiny kernels ----------------
__global__ void zero_kernel(float* o) { o[0] = 0.0f; }

// Wc1[0] = Wroot1[0]+Wroot1[2]  (dst type 0: rels 0,2)
// Wc1[1] = Wroot1[1]+Wroot1[4]  (dst type 1: rels 1,4)
// Wc2    = Wroot2[0]+Wroot2[2]  (dst type 0: rels 0,2)
__global__ void combine_kernel(const float* __restrict__ Wr1, const float* __restrict__ br1,
                               const float* __restrict__ Wr2, const float* __restrict__ br2) {
    int i = blockIdx.x * blockDim.x + threadIdx.x;
    if (i < D * D) {
        g_Wc1[i]         = Wr1[i]         + Wr1[2 * D * D + i];
        g_Wc1[D * D + i] = Wr1[D * D + i] + Wr1[4 * D * D + i];
        g_Wc2[i]         = Wr2[i]         + Wr2[2 * D * D + i];
    }
    if (i < D) {
        g_bc1[i]     = br1[i]     + br1[2 * D + i];
        g_bc1[D + i] = br1[D + i] + br1[4 * D + i];
        g_bc2[i]     = br2[i]     + br2[2 * D + i];
    }
}

// ---------------- SGEMM: C[M=20000, 256] = A[M,256] @ B[256,256] (+bias) ----------------
// 128x128 tile, BK=16, 8x8 per thread, 256 threads.
template <bool RELU_A>
__device__ __forceinline__ void gemm_body(const float* __restrict__ A, const float* __restrict__ B,
                                          const float* __restrict__ bias, float* __restrict__ C) {
    __shared__ __align__(16) float As[16][132];   // [k][m], padded
    __shared__ __align__(16) float Bs[16][128];   // [k][n]

    const int tid = threadIdx.x;
    const int m0 = blockIdx.y * 128;
    const int n0 = blockIdx.x * 128;
    const int tx = tid & 15;
    const int ty = tid >> 4;

    float acc[8][8];
#pragma unroll
    for (int i = 0; i < 8; i++)
#pragma unroll
        for (int j = 0; j < 8; j++) acc[i][j] = 0.0f;

    for (int k0 = 0; k0 < D; k0 += 16) {
        // load A tile (128x16) transposed into As, guard M, optional fused relu
#pragma unroll
        for (int l = 0; l < 2; l++) {
            int idx = tid + l * 256;
            int row = idx >> 2;            // 0..127
            int c4  = (idx & 3) << 2;      // 0,4,8,12
            float4 v = make_float4(0.f, 0.f, 0.f, 0.f);
            int m = m0 + row;
            if (m < NN) v = *(const float4*)(A + (size_t)m * D + k0 + c4);
            if (RELU_A) {
                v.x = fmaxf(v.x, 0.f); v.y = fmaxf(v.y, 0.f);
                v.z = fmaxf(v.z, 0.f); v.w = fmaxf(v.w, 0.f);
            }
            As[c4 + 0][row] = v.x;
            As[c4 + 1][row] = v.y;
            As[c4 + 2][row] = v.z;
            As[c4 + 3][row] = v.w;
        }
        // load B tile (16x128)
#pragma unroll
        for (int l = 0; l < 2; l++) {
            int idx = tid + l * 256;
            int kr = idx >> 5;             // 0..15
            int c4 = (idx & 31) << 2;      // 0..124
            *(float4*)&Bs[kr][c4] = *(const float4*)(B + (size_t)(k0 + kr) * D + n0 + c4);
        }
        __syncthreads();

#pragma unroll
        for (int kk = 0; kk < 16; kk++) {
            float a[8], b[8];
            *(float4*)&a[0] = *(const float4*)&As[kk][ty * 8];
            *(float4*)&a[4] = *(const float4*)&As[kk][ty * 8 + 4];
            *(float4*)&b[0] = *(const float4*)&Bs[kk][tx * 8];
            *(float4*)&b[4] = *(const float4*)&Bs[kk][tx * 8 + 4];
#pragma unroll
            for (int i = 0; i < 8; i++)
#pragma unroll
                for (int j = 0; j < 8; j++) acc[i][j] += a[i] * b[j];
        }
        __syncthreads();
    }

    float bb[8];
#pragma unroll
    for (int j = 0; j < 8; j++) bb[j] = bias ? bias[n0 + tx * 8 + j] : 0.0f;

#pragma unroll
    for (int i = 0; i < 8; i++) {
        int m = m0 + ty * 8 + i;
        if (m < NN) {
            float4 r0, r1;
            r0.x = acc[i][0] + bb[0]; r0.y = acc[i][1] + bb[1];
            r0.z = acc[i][2] + bb[2]; r0.w = acc[i][3] + bb[3];
            r1.x = acc[i][4] + bb[4]; r1.y = acc[i][5] + bb[5];
            r1.z = acc[i][6] + bb[6]; r1.w = acc[i][7] + bb[7];
            *(float4*)(C + (size_t)m * D + n0 + tx * 8)     = r0;
            *(float4*)(C + (size_t)m * D + n0 + tx * 8 + 4) = r1;
        }
    }
}

// Layer 1: 6 GEMM jobs batched via blockIdx.z.
//  job0: h0 = x0 @ (Wroot1[0]+Wroot1[2]) + (b1[0]+b1[2])     (root init, dst 0)
//  job1: h1 = x1 @ (Wroot1[1]+Wroot1[4]) + (b1[1]+b1[4])     (root init, dst 1)
//  job2: y0 = x0 @ Wrel1[0]   (rel 0: 0->0)
//  job3: y1 = x0 @ Wrel1[1]   (rel 1: 0->1)
//  job4: y2 = x1 @ Wrel1[2]   (rel 2: 1->0)
//  job5: y3 = x2 @ Wrel1[4]   (rel 4: 2->1)
__global__ __launch_bounds__(256, 2) void gemm1_kernel(const float* __restrict__ x,
                                                       const float* __restrict__ Wrel1) {
    const float* A; const float* B; const float* bias = nullptr; float* C;
    switch (blockIdx.z) {
        case 0:  A = x;          B = g_Wc1;             bias = g_bc1;     C = g_h0; break;
        case 1:  A = x + ND;     B = g_Wc1 + D * D;     bias = g_bc1 + D; C = g_h1; break;
        case 2:  A = x;          B = Wrel1;                               C = g_y0; break;
        case 3:  A = x;          B = Wrel1 + D * D;                       C = g_y1; break;
        case 4:  A = x + ND;     B = Wrel1 + 2 * D * D;                   C = g_y2; break;
        default: A = x + 2 * ND; B = Wrel1 + 4 * D * D;                   C = g_y3; break;
    }
    gemm_body<false>(A, B, bias, C);
}

// Layer 2 (only dst type 0 is ever read by the loss). ReLU fused into A loads.
//  job0: o2 = relu(h0) @ (Wroot2[0]+Wroot2[2]) + (b2[0]+b2[2])
//  job1: y0 = relu(h0) @ Wrel2[0]   (rel 0: 0->0)
//  job2: y1 = relu(h1) @ Wrel2[2]   (rel 2: 1->0)
__global__ __launch_bounds__(256, 2) void gemm2_kernel(const float* __restrict__ Wrel2) {
    const float* A; const float* B; const float* bias = nullptr; float* C;
    switch (blockIdx.z) {
        case 0:  A = g_h0; B = g_Wc2;           bias = g_bc2; C = g_o2; break;
        case 1:  A = g_h0; B = Wrel2;                         C = g_y0; break;
        default: A = g_h1; B = Wrel2 + 2 * D * D;             C = g_y1; break;
    }
    gemm_body<true>(A, B, bias, C);
}

// ---------------- scatter-add (one warp per edge, vector f32x4 reductions) ----------------
__device__ __forceinline__ void scatter_row(const float* __restrict__ ys, float* __restrict__ od,
                                            int lane) {
#pragma unroll
    for (int h = 0; h < 2; h++) {
        int off = h * 128 + lane * 4;
        float4 v = *(const float4*)(ys + off);
        asm volatile("red.global.add.v4.f32 [%0], {%1, %2, %3, %4};"
                     :: "l"(od + off), "f"(v.x), "f"(v.y), "f"(v.z), "f"(v.w)
                     : "memory");
    }
}

// Layer 1 scatters: rel0 (y0 -> h0), rel1 (y1 -> h1), rel2 (y2 -> h0), rel4 (y3 -> h1)
__global__ void scatter1_kernel(const int* __restrict__ edges) {
    int gw   = (blockIdx.x * blockDim.x + threadIdx.x) >> 5;
    int lane = threadIdx.x & 31;
    int rel = gw / EE;              // 0..3 (4*EE warps exactly)
    int e   = gw - rel * EE;
    const int* ep; const float* ysrc; float* odst;
    switch (rel) {
        case 0:  ep = edges;          ysrc = g_y0; odst = g_h0; break;   // rel 0
        case 1:  ep = edges + 2 * EE; ysrc = g_y1; odst = g_h1; break;   // rel 1
        case 2:  ep = edges + 4 * EE; ysrc = g_y2; odst = g_h0; break;   // rel 2
        default: ep = edges + 8 * EE; ysrc = g_y3; odst = g_h1; break;   // rel 4
    }
    int src = ep[e];
    int dst = ep[EE + e];
    scatter_row(ysrc + (size_t)src * D, odst + (size_t)dst * D, lane);
}

// Layer 2 scatters: rel0 (y0 -> o2), rel2 (y1 -> o2)
__global__ void scatter2_kernel(const int* __restrict__ edges) {
    int gw   = (blockIdx.x * blockDim.x + threadIdx.x) >> 5;
    int lane = threadIdx.x & 31;
    int rel = gw / EE;              // 0..1 (2*EE warps exactly)
    int e   = gw - rel * EE;
    const int* ep; const float* ysrc;
    if (rel == 0) { ep = edges;          ysrc = g_y0; }   // rel 0
    else          { ep = edges + 4 * EE; ysrc = g_y1; }   // rel 2
    int src = ep[e];
    int dst = ep[EE + e];
    scatter_row(ysrc + (size_t)src * D, g_o2 + (size_t)dst * D, lane);
}

// ---------------- loss: mean_i [ logsumexp(o2[i,:]) - o2[i, y[i]] ] ----------------
__global__ void loss_kernel(const int* __restrict__ y, float* __restrict__ out) {
    int gw   = (blockIdx.x * blockDim.x + threadIdx.x) >> 5;   // row, exactly 20000
    int lane = threadIdx.x & 31;
    const float* row = g_o2 + (size_t)gw * D;

    float v[8];
#pragma unroll
    for (int i = 0; i < 8; i++) v[i] = row[lane + 32 * i];

    float m = v[0];
#pragma unroll
    for (int i = 1; i < 8; i++) m = fmaxf(m, v[i]);
#pragma unroll
    for (int o = 16; o; o >>= 1) m = fmaxf(m, __shfl_xor_sync(0xFFFFFFFFu, m, o));

    float s = 0.0f;
#pragma unroll
    for (int i = 0; i < 8; i++) s += expf(v[i] - m);
#pragma unroll
    for (int o = 16; o; o >>= 1) s += __shfl_xor_sync(0xFFFFFFFFu, s, o);

    float nll = (m + logf(s)) - row[y[gw]];

    __shared__ float partial[8];
    if (lane == 0) partial[threadIdx.x >> 5] = nll;
    __syncthreads();
    if (threadIdx.x == 0) {
        float t = 0.0f;
#pragma unroll
        for (int i = 0; i < 8; i++) t += partial[i];
        atomicAdd(out, t * (1.0f / (float)NN));
    }
}

// ---------------- launch ----------------
extern "C" void kernel_launch(void* const* d_in, const int* in_sizes, int n_in,
                              void* d_out, int out_size) {
    const float* x      = (const float*)d_in[0];
    const int*   edges  = (const int*)d_in[1];
    const int*   y      = (const int*)d_in[2];
    const float* Wrel1  = (const float*)d_in[3];
    const float* brel1  = (const float*)d_in[4];
    const float* Wroot1 = (const float*)d_in[5];
    const float* Wrel2  = (const float*)d_in[6];
    const float* brel2  = (const float*)d_in[7];
    const float* Wroot2 = (const float*)d_in[8];
    float* out = (float*)d_out;

    const int MT = (NN + 127) / 128;   // 157 M-tiles

    zero_kernel<<<1, 1>>>(out);
    combine_kernel<<<(D * D + 255) / 256, 256>>>(Wroot1, brel1, Wroot2, brel2);

    gemm1_kernel<<<dim3(2, MT, 6), 256>>>(x, Wrel1);
    scatter1_kernel<<<(4 * EE) / 8, 256>>>(edges);        // 4*320000 warps, 8/block

    gemm2_kernel<<<dim3(2, MT, 3), 256>>>(Wrel2);
    scatter2_kernel<<<(2 * EE) / 8, 256>>>(edges);

    loss_kernel<<<NN / 8, 256>>>(y, out);                 // 2500 blocks, warp per row
}

// round 5
// speedup vs baseline: 1.7343x; 1.7343x over previous
#include <cuda_runtime.h>
#include <math.h>
#include <stdint.h>

#define NN 20000        // nodes per type
#define D  256          // feature dim
#define EE 320000       // edges per relation
#define ND (NN * D)

// ---------------- scratch (device globals: no allocation allowed) ----------------
__device__ __align__(16) float g_h0[ND];      // layer1 out, type 0
__device__ __align__(16) float g_h1[ND];      // layer1 out, type 1
__device__ __align__(16) float g_o2[ND];      // layer2 out, type 0 (logits)
__device__ __align__(16) float g_y0[ND];      // per-relation transformed features
__device__ __align__(16) float g_y1[ND];
__device__ __align__(16) float g_y2[ND];
__device__ __align__(16) float g_y3[ND];
__device__ __align__(16) float g_WT[9][D * D];   // pre-transposed (and combined) weights [n][k]
__device__ float g_bc1[2 * D];
__device__ float g_bc2[D];

// ---------------- tiny kernels ----------------
__global__ void zero_kernel(float* o) { o[0] = 0.0f; }

// Transpose (+ combine root pairs and biases) into g_WT[9][n][k].
//  0: (Wroot1[0]+Wroot1[2])^T   1: (Wroot1[1]+Wroot1[4])^T
//  2: Wrel1[0]^T  3: Wrel1[1]^T  4: Wrel1[2]^T  5: Wrel1[4]^T
//  6: (Wroot2[0]+Wroot2[2])^T   7: Wrel2[0]^T   8: Wrel2[2]^T
__global__ void prep_kernel(const float* __restrict__ Wrel1, const float* __restrict__ brel1,
                            const float* __restrict__ Wroot1, const float* __restrict__ Wrel2,
                            const float* __restrict__ brel2, const float* __restrict__ Wroot2) {
    __shared__ float t[32][33];
    int j = blockIdx.z;
    const float* S0; const float* S1 = nullptr;
    switch (j) {
        case 0:  S0 = Wroot1;             S1 = Wroot1 + 2 * D * D; break;
        case 1:  S0 = Wroot1 + D * D;     S1 = Wroot1 + 4 * D * D; break;
        case 2:  S0 = Wrel1;              break;
        case 3:  S0 = Wrel1 + D * D;      break;
        case 4:  S0 = Wrel1 + 2 * D * D;  break;
        case 5:  S0 = Wrel1 + 4 * D * D;  break;
        case 6:  S0 = Wroot2;             S1 = Wroot2 + 2 * D * D; break;
        case 7:  S0 = Wrel2;              break;
        default: S0 = Wrel2 + 2 * D * D;  break;
    }
    int k0 = blockIdx.y * 32, n0 = blockIdx.x * 32;
    int tx = threadIdx.x, ty = threadIdx.y;     // 32 x 8
#pragma unroll
    for (int r = ty; r < 32; r += 8) {
        float v = S0[(size_t)(k0 + r) * D + n0 + tx];
        if (S1) v += S1[(size_t)(k0 + r) * D + n0 + tx];
        t[r][tx] = v;
    }
    __syncthreads();
    float* WT = g_WT[j];
#pragma unroll
    for (int r = ty; r < 32; r += 8)
        WT[(size_t)(n0 + r) * D + k0 + tx] = t[tx][r];

    if (blockIdx.x == 0 && blockIdx.y == 0 && j == 0) {
        int i = ty * 32 + tx;
        if (i < D) {
            g_bc1[i]     = brel1[i]         + brel1[2 * D + i];
            g_bc1[D + i] = brel1[D + i]     + brel1[4 * D + i];
            g_bc2[i]     = brel2[i]         + brel2[2 * D + i];
        }
    }
}

// ---------------- tf32 mma.sync GEMM: C[M,256] = A[M,256] @ W (+bias) ----------------
// CTA tile 128x128, BK=32. 8 warps in 4x2 grid; warp tile 32x64 = 2x8 m16n8k8 frags.
// SMEM stride 36 floats -> fragment LDS bank = (4*row + col) % 32, conflict-free.

__device__ __forceinline__ uint32_t f2tf32(float v) {
    uint32_t u;
    asm("cvt.rna.tf32.f32 %0, %1;" : "=r"(u) : "f"(v));
    return u;
}

__device__ __forceinline__ void mma_tf32(float* c, const uint32_t* a, const uint32_t* b) {
    asm volatile(
        "mma.sync.aligned.m16n8k8.row.col.f32.tf32.tf32.f32 "
        "{%0,%1,%2,%3}, {%4,%5,%6,%7}, {%8,%9}, {%0,%1,%2,%3};"
        : "+f"(c[0]), "+f"(c[1]), "+f"(c[2]), "+f"(c[3])
        : "r"(a[0]), "r"(a[1]), "r"(a[2]), "r"(a[3]), "r"(b[0]), "r"(b[1]));
}

template <bool RELU>
__device__ __forceinline__ void gemm_body(const float* __restrict__ A,
                                          const float* __restrict__ WT,
                                          const float* __restrict__ bias,
                                          float* __restrict__ C) {
    __shared__ float As[128][36];   // [m][k], tf32 bit patterns
    __shared__ float Bs[128][36];   // [n][k]

    const int tid  = threadIdx.x;
    const int wid  = tid >> 5;
    const int lane = tid & 31;
    const int gid  = lane >> 2;     // group id (rows of fragments)
    const int tig  = lane & 3;      // thread-in-group (cols of fragments)
    const int m0 = blockIdx.x * 128;
    const int n0 = blockIdx.y * 128;
    const int wm = (wid & 3) * 32;  // warp m-offset within CTA tile
    const int wn = (wid >> 2) * 64; // warp n-offset within CTA tile

    float acc[2][8][4];
#pragma unroll
    for (int mt = 0; mt < 2; mt++)
#pragma unroll
        for (int nt = 0; nt < 8; nt++)
#pragma unroll
            for (int q = 0; q < 4; q++) acc[mt][nt][q] = 0.0f;

    for (int kc = 0; kc < 8; kc++) {
        const int k0g = kc * 32;
        // ---- stage A tile: 128 x 32 floats, coalesced float4 loads, scalar STS ----
#pragma unroll
        for (int i = 0; i < 4; i++) {
            int idx = tid + i * 256;
            int row = idx >> 3;
            int c4  = (idx & 7) << 2;
            float4 v = make_float4(0.f, 0.f, 0.f, 0.f);
            int m = m0 + row;
            if (m < NN) v = *(const float4*)(A + (size_t)m * D + k0g + c4);
            if (RELU) {
                v.x = fmaxf(v.x, 0.f); v.y = fmaxf(v.y, 0.f);
                v.z = fmaxf(v.z, 0.f); v.w = fmaxf(v.w, 0.f);
            }
            As[row][c4 + 0] = __uint_as_float(f2tf32(v.x));
            As[row][c4 + 1] = __uint_as_float(f2tf32(v.y));
            As[row][c4 + 2] = __uint_as_float(f2tf32(v.z));
            As[row][c4 + 3] = __uint_as_float(f2tf32(v.w));
        }
        // ---- stage B tile: 128 n-rows x 32 k ----
#pragma unroll
        for (int i = 0; i < 4; i++) {
            int idx = tid + i * 256;
            int row = idx >> 3;
            int c4  = (idx & 7) << 2;
            float4 v = *(const float4*)(WT + (size_t)(n0 + row) * D + k0g + c4);
            Bs[row][c4 + 0] = __uint_as_float(f2tf32(v.x));
            Bs[row][c4 + 1] = __uint_as_float(f2tf32(v.y));
            Bs[row][c4 + 2] = __uint_as_float(f2tf32(v.z));
            Bs[row][c4 + 3] = __uint_as_float(f2tf32(v.w));
        }
        __syncthreads();

#pragma unroll
        for (int ks = 0; ks < 4; ks++) {
            const int k0 = ks * 8;
            uint32_t af[2][4], bf[8][2];
#pragma unroll
            for (int mt = 0; mt < 2; mt++) {
                int r = wm + mt * 16 + gid;
                af[mt][0] = __float_as_uint(As[r][k0 + tig]);
                af[mt][1] = __float_as_uint(As[r + 8][k0 + tig]);
                af[mt][2] = __float_as_uint(As[r][k0 + tig + 4]);
                af[mt][3] = __float_as_uint(As[r + 8][k0 + tig + 4]);
            }
#pragma unroll
            for (int nt = 0; nt < 8; nt++) {
                int c = wn + nt * 8 + gid;
                bf[nt][0] = __float_as_uint(Bs[c][k0 + tig]);
                bf[nt][1] = __float_as_uint(Bs[c][k0 + tig + 4]);
            }
#pragma unroll
            for (int mt = 0; mt < 2; mt++)
#pragma unroll
                for (int nt = 0; nt < 8; nt++)
                    mma_tf32(acc[mt][nt], af[mt], bf[nt]);
        }
        __syncthreads();
    }

    // ---- epilogue: c0/c1 -> (row=gid, n=2*tig), c2/c3 -> (row=gid+8) ----
#pragma unroll
    for (int mt = 0; mt < 2; mt++) {
        int m_lo = m0 + wm + mt * 16 + gid;
        int m_hi = m_lo + 8;
#pragma unroll
        for (int nt = 0; nt < 8; nt++) {
            int n = n0 + wn + nt * 8 + tig * 2;
            float b0 = bias ? bias[n] : 0.f;
            float b1 = bias ? bias[n + 1] : 0.f;
            if (m_lo < NN) {
                float2 v = make_float2(acc[mt][nt][0] + b0, acc[mt][nt][1] + b1);
                *(float2*)(C + (size_t)m_lo * D + n) = v;
            }
            if (m_hi < NN) {
                float2 v = make_float2(acc[mt][nt][2] + b0, acc[mt][nt][3] + b1);
                *(float2*)(C + (size_t)m_hi * D + n) = v;
            }
        }
    }
}

// Layer 1 (6 jobs): root GEMMs for dst 0/1 + the 4 needed rel GEMMs.
__global__ __launch_bounds__(256, 2) void gemm1_tc(const float* __restrict__ x) {
    const float* A; const float* B; const float* bias = nullptr; float* C;
    switch (blockIdx.z) {
        case 0:  A = x;          B = g_WT[0]; bias = g_bc1;     C = g_h0; break;
        case 1:  A = x + ND;     B = g_WT[1]; bias = g_bc1 + D; C = g_h1; break;
        case 2:  A = x;          B = g_WT[2];                   C = g_y0; break;
        case 3:  A = x;          B = g_WT[3];                   C = g_y1; break;
        case 4:  A = x + ND;     B = g_WT[4];                   C = g_y2; break;
        default: A = x + 2 * ND; B = g_WT[5];                   C = g_y3; break;
    }
    gemm_body<false>(A, B, bias, C);
}

// Layer 2 (3 jobs; only dst type 0 feeds the loss). ReLU fused into A staging.
__global__ __launch_bounds__(256, 2) void gemm2_tc() {
    const float* A; const float* B; const float* bias = nullptr; float* C;
    switch (blockIdx.z) {
        case 0:  A = g_h0; B = g_WT[6]; bias = g_bc2; C = g_o2; break;
        case 1:  A = g_h0; B = g_WT[7];               C = g_y0; break;
        default: A = g_h1; B = g_WT[8];               C = g_y1; break;
    }
    gemm_body<true>(A, B, bias, C);
}

// ---------------- scatter-add (one warp per edge, vector f32x4 reductions) ----------------
__device__ __forceinline__ void scatter_row(const float* __restrict__ ys, float* __restrict__ od,
                                            int lane) {
#pragma unroll
    for (int h = 0; h < 2; h++) {
        int off = h * 128 + lane * 4;
        float4 v = *(const float4*)(ys + off);
        asm volatile("red.global.add.v4.f32 [%0], {%1, %2, %3, %4};"
                     :: "l"(od + off), "f"(v.x), "f"(v.y), "f"(v.z), "f"(v.w)
                     : "memory");
    }
}

__global__ void scatter1_kernel(const int* __restrict__ edges) {
    int gw   = (blockIdx.x * blockDim.x + threadIdx.x) >> 5;
    int lane = threadIdx.x & 31;
    int rel = gw / EE;
    int e   = gw - rel * EE;
    const int* ep; const float* ysrc; float* odst;
    switch (rel) {
        case 0:  ep = edges;          ysrc = g_y0; odst = g_h0; break;   // rel 0: 0->0
        case 1:  ep = edges + 2 * EE; ysrc = g_y1; odst = g_h1; break;   // rel 1: 0->1
        case 2:  ep = edges + 4 * EE; ysrc = g_y2; odst = g_h0; break;   // rel 2: 1->0
        default: ep = edges + 8 * EE; ysrc = g_y3; odst = g_h1; break;   // rel 4: 2->1
    }
    int src = ep[e];
    int dst = ep[EE + e];
    scatter_row(ysrc + (size_t)src * D, odst + (size_t)dst * D, lane);
}

__global__ void scatter2_kernel(const int* __restrict__ edges) {
    int gw   = (blockIdx.x * blockDim.x + threadIdx.x) >> 5;
    int lane = threadIdx.x & 31;
    int rel = gw / EE;
    int e   = gw - rel * EE;
    const int* ep; const float* ysrc;
    if (rel == 0) { ep = edges;          ysrc = g_y0; }   // rel 0: 0->0
    else          { ep = edges + 4 * EE; ysrc = g_y1; }   // rel 2: 1->0
    int src = ep[e];
    int dst = ep[EE + e];
    scatter_row(ysrc + (size_t)src * D, g_o2 + (size_t)dst * D, lane);
}

// ---------------- loss: mean_i [ logsumexp(o2[i,:]) - o2[i, y[i]] ] ----------------
__global__ void loss_kernel(const int* __restrict__ y, float* __restrict__ out) {
    int gw   = (blockIdx.x * blockDim.x + threadIdx.x) >> 5;
    int lane = threadIdx.x & 31;
    const float* row = g_o2 + (size_t)gw * D;

    float v[8];
#pragma unroll
    for (int i = 0; i < 8; i++) v[i] = row[lane + 32 * i];

    float m = v[0];
#pragma unroll
    for (int i = 1; i < 8; i++) m = fmaxf(m, v[i]);
#pragma unroll
    for (int o = 16; o; o >>= 1) m = fmaxf(m, __shfl_xor_sync(0xFFFFFFFFu, m, o));

    float s = 0.0f;
#pragma unroll
    for (int i = 0; i < 8; i++) s += expf(v[i] - m);
#pragma unroll
    for (int o = 16; o; o >>= 1) s += __shfl_xor_sync(0xFFFFFFFFu, s, o);

    float nll = (m + logf(s)) - row[y[gw]];

    __shared__ float partial[8];
    if (lane == 0) partial[threadIdx.x >> 5] = nll;
    __syncthreads();
    if (threadIdx.x == 0) {
        float t = 0.0f;
#pragma unroll
        for (int i = 0; i < 8; i++) t += partial[i];
        atomicAdd(out, t * (1.0f / (float)NN));
    }
}

// ---------------- launch ----------------
extern "C" void kernel_launch(void* const* d_in, const int* in_sizes, int n_in,
                              void* d_out, int out_size) {
    const float* x      = (const float*)d_in[0];
    const int*   edges  = (const int*)d_in[1];
    const int*   y      = (const int*)d_in[2];
    const float* Wrel1  = (const float*)d_in[3];
    const float* brel1  = (const float*)d_in[4];
    const float* Wroot1 = (const float*)d_in[5];
    const float* Wrel2  = (const float*)d_in[6];
    const float* brel2  = (const float*)d_in[7];
    const float* Wroot2 = (const float*)d_in[8];
    float* out = (float*)d_out;

    const int MT = (NN + 127) / 128;   // 157 M-tiles

    zero_kernel<<<1, 1>>>(out);
    prep_kernel<<<dim3(8, 8, 9), dim3(32, 8)>>>(Wrel1, brel1, Wroot1, Wrel2, brel2, Wroot2);

    gemm1_tc<<<dim3(MT, 2, 6), 256>>>(x);
    scatter1_kernel<<<(4 * EE) / 8, 256>>>(edges);

    gemm2_tc<<<dim3(MT, 2, 3), 256>>>();
    scatter2_kernel<<<(2 * EE) / 8, 256>>>(edges);

    loss_kernel<<<NN / 8, 256>>>(y, out);
}

// round 6
// speedup vs baseline: 2.7032x; 1.5586x over previous
#include <cuda_runtime.h>
#include <cuda_bf16.h>
#include <math.h>
#include <stdint.h>

#define NN 20000        // nodes per type
#define D  256          // feature dim
#define EE 320000       // edges per relation
#define ND (NN * D)

// ---------------- scratch (device globals: no allocation allowed) ----------------
__device__ __align__(16) float g_h0[ND];      // layer1 out, type 0
__device__ __align__(16) float g_h1[ND];      // layer1 out, type 1
__device__ __align__(16) float g_o2[ND];      // layer2 out, type 0 (logits)
__device__ __align__(16) __nv_bfloat16 g_yb0[ND];   // bf16 transformed features
__device__ __align__(16) __nv_bfloat16 g_yb1[ND];
__device__ __align__(16) __nv_bfloat16 g_yb2[ND];
__device__ __align__(16) __nv_bfloat16 g_yb3[ND];
__device__ __align__(16) float g_WT[9][D * D];   // pre-transposed (combined) weights [n][k]
__device__ float g_bc1[2 * D];
__device__ float g_bc2[D];

// CSR state: group 0 = dst-type-0 edges (rel0 tag0, rel2 tag1)  [reused by layer 2]
//            group 1 = dst-type-1 edges (rel1 tag0, rel4 tag1)
__device__ int g_cnt[2][NN];
__device__ int g_off[2][NN + 1];
__device__ int g_cur[2][NN];
__device__ int g_rec[2][2 * EE];

// ---------------- tiny kernels ----------------
__global__ void zero_kernel(float* o) { o[0] = 0.0f; }

__global__ void zero_cnt_kernel() {
    int i = blockIdx.x * blockDim.x + threadIdx.x;
    if (i < 2 * NN) ((int*)g_cnt)[i] = 0;
}

// segment s -> (rel k, group, tag):  s0:(0,0,0)  s1:(2,0,1)  s2:(1,1,0)  s3:(4,1,1)
__device__ __forceinline__ void seg_map(int s, int& k, int& grp, int& tag) {
    switch (s) {
        case 0:  k = 0; grp = 0; tag = 0; break;
        case 1:  k = 2; grp = 0; tag = 1; break;
        case 2:  k = 1; grp = 1; tag = 0; break;
        default: k = 4; grp = 1; tag = 1; break;
    }
}

__global__ void hist_kernel(const int* __restrict__ edges) {
    int idx = blockIdx.x * blockDim.x + threadIdx.x;
    if (idx >= 4 * EE) return;
    int s = idx / EE, e = idx - s * EE;
    int k, grp, tag; seg_map(s, k, grp, tag);
    int dst = edges[k * 2 * EE + EE + e];
    atomicAdd(&g_cnt[grp][dst], 1);
}

__global__ void scan_kernel() {
    const int grp = blockIdx.x;
    const int tid = threadIdx.x;            // 1024
    __shared__ int sh[1024];
    const int CH = (NN + 1023) / 1024;      // 20
    int base = tid * CH;
    int s = 0;
#pragma unroll
    for (int i = 0; i < CH; i++) {
        int idx = base + i;
        if (idx < NN) s += g_cnt[grp][idx];
    }
    sh[tid] = s;
    __syncthreads();
    for (int off = 1; off < 1024; off <<= 1) {
        int v = 0;
        if (tid >= off) v = sh[tid - off];
        __syncthreads();
        if (tid >= off) sh[tid] += v;
        __syncthreads();
    }
    int run = (tid ? sh[tid - 1] : 0);
#pragma unroll
    for (int i = 0; i < CH; i++) {
        int idx = base + i;
        if (idx < NN) {
            g_off[grp][idx] = run;
            g_cur[grp][idx] = run;
            run += g_cnt[grp][idx];
        }
    }
    if (tid == 1023) g_off[grp][NN] = sh[1023];
}

__global__ void fill_kernel(const int* __restrict__ edges) {
    int idx = blockIdx.x * blockDim.x + threadIdx.x;
    if (idx >= 4 * EE) return;
    int s = idx / EE, e = idx - s * EE;
    int k, grp, tag; seg_map(s, k, grp, tag);
    int src = edges[k * 2 * EE + e];
    int dst = edges[k * 2 * EE + EE + e];
    int pos = atomicAdd(&g_cur[grp][dst], 1);
    g_rec[grp][pos] = (int)((unsigned)src | ((unsigned)tag << 31));
}

// Transpose (+ combine root pairs and biases) into g_WT[9][n][k].
//  0:(Wroot1[0]+Wroot1[2])^T  1:(Wroot1[1]+Wroot1[4])^T
//  2:Wrel1[0]^T 3:Wrel1[1]^T 4:Wrel1[2]^T 5:Wrel1[4]^T
//  6:(Wroot2[0]+Wroot2[2])^T  7:Wrel2[0]^T 8:Wrel2[2]^T
__global__ void prep_kernel(const float* __restrict__ Wrel1, const float* __restrict__ brel1,
                            const float* __restrict__ Wroot1, const float* __restrict__ Wrel2,
                            const float* __restrict__ brel2, const float* __restrict__ Wroot2) {
    __shared__ float t[32][33];
    int j = blockIdx.z;
    const float* S0; const float* S1 = nullptr;
    switch (j) {
        case 0:  S0 = Wroot1;             S1 = Wroot1 + 2 * D * D; break;
        case 1:  S0 = Wroot1 + D * D;     S1 = Wroot1 + 4 * D * D; break;
        case 2:  S0 = Wrel1;              break;
        case 3:  S0 = Wrel1 + D * D;      break;
        case 4:  S0 = Wrel1 + 2 * D * D;  break;
        case 5:  S0 = Wrel1 + 4 * D * D;  break;
        case 6:  S0 = Wroot2;             S1 = Wroot2 + 2 * D * D; break;
        case 7:  S0 = Wrel2;              break;
        default: S0 = Wrel2 + 2 * D * D;  break;
    }
    int k0 = blockIdx.y * 32, n0 = blockIdx.x * 32;
    int tx = threadIdx.x, ty = threadIdx.y;     // 32 x 8
#pragma unroll
    for (int r = ty; r < 32; r += 8) {
        float v = S0[(size_t)(k0 + r) * D + n0 + tx];
        if (S1) v += S1[(size_t)(k0 + r) * D + n0 + tx];
        t[r][tx] = v;
    }
    __syncthreads();
    float* WT = g_WT[j];
#pragma unroll
    for (int r = ty; r < 32; r += 8)
        WT[(size_t)(n0 + r) * D + k0 + tx] = t[tx][r];

    if (blockIdx.x == 0 && blockIdx.y == 0 && j == 0) {
        int i = ty * 32 + tx;
        if (i < D) {
            g_bc1[i]     = brel1[i]         + brel1[2 * D + i];
            g_bc1[D + i] = brel1[D + i]     + brel1[4 * D + i];
            g_bc2[i]     = brel2[i]         + brel2[2 * D + i];
        }
    }
}

// ---------------- tf32 mma.sync GEMM: C[M,256] = A[M,256] @ W (+bias) ----------------
// CTA tile 128x128, BK=32. 8 warps 4x2; warp tile 32x64 = 2x8 m16n8k8 frags.

__device__ __forceinline__ uint32_t f2tf32(float v) {
    uint32_t u;
    asm("cvt.rna.tf32.f32 %0, %1;" : "=r"(u) : "f"(v));
    return u;
}

__device__ __forceinline__ void mma_tf32(float* c, const uint32_t* a, const uint32_t* b) {
    asm volatile(
        "mma.sync.aligned.m16n8k8.row.col.f32.tf32.tf32.f32 "
        "{%0,%1,%2,%3}, {%4,%5,%6,%7}, {%8,%9}, {%0,%1,%2,%3};"
        : "+f"(c[0]), "+f"(c[1]), "+f"(c[2]), "+f"(c[3])
        : "r"(a[0]), "r"(a[1]), "r"(a[2]), "r"(a[3]), "r"(b[0]), "r"(b[1]));
}

template <bool RELU, bool BF16OUT>
__device__ __forceinline__ void gemm_body(const float* __restrict__ A,
                                          const float* __restrict__ WT,
                                          const float* __restrict__ bias,
                                          float* __restrict__ Cf,
                                          __nv_bfloat16* __restrict__ Cb) {
    __shared__ float As[128][36];   // [m][k]
    __shared__ float Bs[128][36];   // [n][k]

    const int tid  = threadIdx.x;
    const int wid  = tid >> 5;
    const int lane = tid & 31;
    const int gid  = lane >> 2;
    const int tig  = lane & 3;
    const int m0 = blockIdx.x * 128;
    const int n0 = blockIdx.y * 128;
    const int wm = (wid & 3) * 32;
    const int wn = (wid >> 2) * 64;

    float acc[2][8][4];
#pragma unroll
    for (int mt = 0; mt < 2; mt++)
#pragma unroll
        for (int nt = 0; nt < 8; nt++)
#pragma unroll
            for (int q = 0; q < 4; q++) acc[mt][nt][q] = 0.0f;

    for (int kc = 0; kc < 8; kc++) {
        const int k0g = kc * 32;
#pragma unroll
        for (int i = 0; i < 4; i++) {
            int idx = tid + i * 256;
            int row = idx >> 3;
            int c4  = (idx & 7) << 2;
            float4 v = make_float4(0.f, 0.f, 0.f, 0.f);
            int m = m0 + row;
            if (m < NN) v = *(const float4*)(A + (size_t)m * D + k0g + c4);
            if (RELU) {
                v.x = fmaxf(v.x, 0.f); v.y = fmaxf(v.y, 0.f);
                v.z = fmaxf(v.z, 0.f); v.w = fmaxf(v.w, 0.f);
            }
            As[row][c4 + 0] = __uint_as_float(f2tf32(v.x));
            As[row][c4 + 1] = __uint_as_float(f2tf32(v.y));
            As[row][c4 + 2] = __uint_as_float(f2tf32(v.z));
            As[row][c4 + 3] = __uint_as_float(f2tf32(v.w));
        }
#pragma unroll
        for (int i = 0; i < 4; i++) {
            int idx = tid + i * 256;
            int row = idx >> 3;
            int c4  = (idx & 7) << 2;
            float4 v = *(const float4*)(WT + (size_t)(n0 + row) * D + k0g + c4);
            Bs[row][c4 + 0] = __uint_as_float(f2tf32(v.x));
            Bs[row][c4 + 1] = __uint_as_float(f2tf32(v.y));
            Bs[row][c4 + 2] = __uint_as_float(f2tf32(v.z));
            Bs[row][c4 + 3] = __uint_as_float(f2tf32(v.w));
        }
        __syncthreads();

#pragma unroll
        for (int ks = 0; ks < 4; ks++) {
            const int k0 = ks * 8;
            uint32_t af[2][4], bf[8][2];
#pragma unroll
            for (int mt = 0; mt < 2; mt++) {
                int r = wm + mt * 16 + gid;
                af[mt][0] = __float_as_uint(As[r][k0 + tig]);
                af[mt][1] = __float_as_uint(As[r + 8][k0 + tig]);
                af[mt][2] = __float_as_uint(As[r][k0 + tig + 4]);
                af[mt][3] = __float_as_uint(As[r + 8][k0 + tig + 4]);
            }
#pragma unroll
            for (int nt = 0; nt < 8; nt++) {
                int c = wn + nt * 8 + gid;
                bf[nt][0] = __float_as_uint(Bs[c][k0 + tig]);
                bf[nt][1] = __float_as_uint(Bs[c][k0 + tig + 4]);
            }
#pragma unroll
            for (int mt = 0; mt < 2; mt++)
#pragma unroll
                for (int nt = 0; nt < 8; nt++)
                    mma_tf32(acc[mt][nt], af[mt], bf[nt]);
        }
        __syncthreads();
    }

#pragma unroll
    for (int mt = 0; mt < 2; mt++) {
        int m_lo = m0 + wm + mt * 16 + gid;
        int m_hi = m_lo + 8;
#pragma unroll
        for (int nt = 0; nt < 8; nt++) {
            int n = n0 + wn + nt * 8 + tig * 2;
            if (BF16OUT) {
                if (m_lo < NN)
                    *(__nv_bfloat162*)(Cb + (size_t)m_lo * D + n) =
                        __float22bfloat162_rn(make_float2(acc[mt][nt][0], acc[mt][nt][1]));
                if (m_hi < NN)
                    *(__nv_bfloat162*)(Cb + (size_t)m_hi * D + n) =
                        __float22bfloat162_rn(make_float2(acc[mt][nt][2], acc[mt][nt][3]));
            } else {
                float b0 = bias ? bias[n] : 0.f;
                float b1 = bias ? bias[n + 1] : 0.f;
                if (m_lo < NN)
                    *(float2*)(Cf + (size_t)m_lo * D + n) =
                        make_float2(acc[mt][nt][0] + b0, acc[mt][nt][1] + b1);
                if (m_hi < NN)
                    *(float2*)(Cf + (size_t)m_hi * D + n) =
                        make_float2(acc[mt][nt][2] + b0, acc[mt][nt][3] + b1);
            }
        }
    }
}

// Layer 1 (6 jobs): roots (fp32+bias) + 4 rel GEMMs (bf16 out).
//  z2: x0@Wrel1[0] -> yb0 (grpA tag0)   z3: x0@Wrel1[1] -> yb2 (grpB tag0)
//  z4: x1@Wrel1[2] -> yb1 (grpA tag1)   z5: x2@Wrel1[4] -> yb3 (grpB tag1)
__global__ __launch_bounds__(256, 2) void gemm1_tc(const float* __restrict__ x) {
    switch (blockIdx.z) {
        case 0:  gemm_body<false, false>(x,          g_WT[0], g_bc1,     g_h0, nullptr); break;
        case 1:  gemm_body<false, false>(x + ND,     g_WT[1], g_bc1 + D, g_h1, nullptr); break;
        case 2:  gemm_body<false, true >(x,          g_WT[2], nullptr, nullptr, g_yb0); break;
        case 3:  gemm_body<false, true >(x,          g_WT[3], nullptr, nullptr, g_yb2); break;
        case 4:  gemm_body<false, true >(x + ND,     g_WT[4], nullptr, nullptr, g_yb1); break;
        default: gemm_body<false, true >(x + 2 * ND, g_WT[5], nullptr, nullptr, g_yb3); break;
    }
}

// Layer 2 (3 jobs; only dst type 0 feeds the loss). ReLU fused into A staging.
//  z1: relu(h0)@Wrel2[0] -> yb0 (tag0)   z2: relu(h1)@Wrel2[2] -> yb1 (tag1)
__global__ __launch_bounds__(256, 2) void gemm2_tc() {
    switch (blockIdx.z) {
        case 0:  gemm_body<true, false>(g_h0, g_WT[6], g_bc2, g_o2, nullptr); break;
        case 1:  gemm_body<true, true >(g_h0, g_WT[7], nullptr, nullptr, g_yb0); break;
        default: gemm_body<true, true >(g_h1, g_WT[8], nullptr, nullptr, g_yb1); break;
    }
}

// ---------------- CSR gather: one warp per dst node ----------------
__device__ __forceinline__ void accum_row(float* acc, const __nv_bfloat16* __restrict__ y0,
                                          const __nv_bfloat16* __restrict__ y1,
                                          int rec, int lane) {
    const __nv_bfloat16* yb = (rec < 0) ? y1 : y0;
    int src = rec & 0x7fffffff;
    uint4 v = *(const uint4*)(yb + (size_t)src * D + lane * 8);
    const __nv_bfloat162* p = (const __nv_bfloat162*)&v;
    float2 f0 = __bfloat1622float2(p[0]);
    float2 f1 = __bfloat1622float2(p[1]);
    float2 f2 = __bfloat1622float2(p[2]);
    float2 f3 = __bfloat1622float2(p[3]);
    acc[0] += f0.x; acc[1] += f0.y; acc[2] += f1.x; acc[3] += f1.y;
    acc[4] += f2.x; acc[5] += f2.y; acc[6] += f3.x; acc[7] += f3.y;
}

__device__ __forceinline__ void gather_node(int grp, int node,
                                            const __nv_bfloat16* __restrict__ y0,
                                            const __nv_bfloat16* __restrict__ y1,
                                            float* __restrict__ tgt, int lane) {
    const int* __restrict__ recs = g_rec[grp];
    int beg = g_off[grp][node];
    int end = g_off[grp][node + 1];

    float acc[8] = {0.f, 0.f, 0.f, 0.f, 0.f, 0.f, 0.f, 0.f};

    for (int base = beg; base < end; base += 32) {
        int m = end - base;
        if (m > 32) m = 32;
        int rec = 0;
        if (lane < m) rec = recs[base + lane];
        int j = 0;
        for (; j + 4 <= m; j += 4) {
            int r0 = __shfl_sync(0xFFFFFFFFu, rec, j);
            int r1 = __shfl_sync(0xFFFFFFFFu, rec, j + 1);
            int r2 = __shfl_sync(0xFFFFFFFFu, rec, j + 2);
            int r3 = __shfl_sync(0xFFFFFFFFu, rec, j + 3);
            accum_row(acc, y0, y1, r0, lane);
            accum_row(acc, y0, y1, r1, lane);
            accum_row(acc, y0, y1, r2, lane);
            accum_row(acc, y0, y1, r3, lane);
        }
        for (; j < m; j++) {
            int r = __shfl_sync(0xFFFFFFFFu, rec, j);
            accum_row(acc, y0, y1, r, lane);
        }
    }

    float* tp = tgt + (size_t)node * D + lane * 8;
    float4 a = *(float4*)tp;
    float4 b = *(float4*)(tp + 4);
    a.x += acc[0]; a.y += acc[1]; a.z += acc[2]; a.w += acc[3];
    b.x += acc[4]; b.y += acc[5]; b.z += acc[6]; b.w += acc[7];
    *(float4*)tp = a;
    *(float4*)(tp + 4) = b;
}

__global__ void gather1_kernel() {
    int gw   = (blockIdx.x * blockDim.x + threadIdx.x) >> 5;   // 0..39999
    int lane = threadIdx.x & 31;
    int grp  = gw >= NN;
    int node = gw - grp * NN;
    if (grp == 0) gather_node(0, node, g_yb0, g_yb1, g_h0, lane);
    else          gather_node(1, node, g_yb2, g_yb3, g_h1, lane);
}

__global__ void gather2_kernel() {
    int gw   = (blockIdx.x * blockDim.x + threadIdx.x) >> 5;   // 0..19999
    int lane = threadIdx.x & 31;
    gather_node(0, gw, g_yb0, g_yb1, g_o2, lane);
}

// ---------------- loss: mean_i [ logsumexp(o2[i,:]) - o2[i, y[i]] ] ----------------
__global__ void loss_kernel(const int* __restrict__ y, float* __restrict__ out) {
    int gw   = (blockIdx.x * blockDim.x + threadIdx.x) >> 5;
    int lane = threadIdx.x & 31;
    const float* row = g_o2 + (size_t)gw * D;

    float v[8];
#pragma unroll
    for (int i = 0; i < 8; i++) v[i] = row[lane + 32 * i];

    float m = v[0];
#pragma unroll
    for (int i = 1; i < 8; i++) m = fmaxf(m, v[i]);
#pragma unroll
    for (int o = 16; o; o >>= 1) m = fmaxf(m, __shfl_xor_sync(0xFFFFFFFFu, m, o));

    float s = 0.0f;
#pragma unroll
    for (int i = 0; i < 8; i++) s += expf(v[i] - m);
#pragma unroll
    for (int o = 16; o; o >>= 1) s += __shfl_xor_sync(0xFFFFFFFFu, s, o);

    float nll = (m + logf(s)) - row[y[gw]];

    __shared__ float partial[8];
    if (lane == 0) partial[threadIdx.x >> 5] = nll;
    __syncthreads();
    if (threadIdx.x == 0) {
        float t = 0.0f;
#pragma unroll
        for (int i = 0; i < 8; i++) t += partial[i];
        atomicAdd(out, t * (1.0f / (float)NN));
    }
}

// ---------------- launch ----------------
extern "C" void kernel_launch(void* const* d_in, const int* in_sizes, int n_in,
                              void* d_out, int out_size) {
    const float* x      = (const float*)d_in[0];
    const int*   edges  = (const int*)d_in[1];
    const int*   y      = (const int*)d_in[2];
    const float* Wrel1  = (const float*)d_in[3];
    const float* brel1  = (const float*)d_in[4];
    const float* Wroot1 = (const float*)d_in[5];
    const float* Wrel2  = (const float*)d_in[6];
    const float* brel2  = (const float*)d_in[7];
    const float* Wroot2 = (const float*)d_in[8];
    float* out = (float*)d_out;

    const int MT = (NN + 127) / 128;   // 157 M-tiles

    zero_kernel<<<1, 1>>>(out);

    // CSR build (independent of GEMMs, runs up front)
    zero_cnt_kernel<<<(2 * NN + 255) / 256, 256>>>();
    hist_kernel<<<(4 * EE + 255) / 256, 256>>>(edges);
    scan_kernel<<<2, 1024>>>();
    fill_kernel<<<(4 * EE + 255) / 256, 256>>>(edges);

    prep_kernel<<<dim3(8, 8, 9), dim3(32, 8)>>>(Wrel1, brel1, Wroot1, Wrel2, brel2, Wroot2);

    gemm1_tc<<<dim3(MT, 2, 6), 256>>>(x);
    gather1_kernel<<<(2 * NN * 32) / 256, 256>>>();     // 5000 blocks

    gemm2_tc<<<dim3(MT, 2, 3), 256>>>();
    gather2_kernel<<<(NN * 32) / 256, 256>>>();         // 2500 blocks

    loss_kernel<<<NN / 8, 256>>>(y, out);
}